// round 9
// baseline (speedup 1.0000x reference)
#include <cuda_runtime.h>
#include <cuda_bf16.h>
#include <cstdint>

// Problem constants
#define NN   10000
#define EE   320000
#define BB   64
#define IN_C 128
#define ECH  64
#define HID  256
#define MLPD 512
#define NCL  4
#define KMAX 576
#define ZDIM (HID + 1 + IN_C)   // 385

// GEMM tiling
#define BM 64
#define BN 128
#define ASTR 80
#define O_AHI 0
#define O_ALO (BM * ASTR)
#define O_BHI (2 * BM * ASTR)
#define O_BLO (2 * BM * ASTR + BN * ASTR)
#define BUFSZ (2 * BM * ASTR + 2 * BN * ASTR)   // 30720
#define GEMM_SMEM (2 * BUFSZ)                   // 61440
#define NTILES (((NN + BM - 1) / BM) * 2)       // 314

// ---------------- scratch ----------------------------------------------------
__device__ __align__(16) __nv_bfloat16 g_Xhi[NN * KMAX];
__device__ __align__(16) __nv_bfloat16 g_Xlo[NN * KMAX];
__device__ __align__(16) __nv_bfloat16 g_Wthi[3 * HID * KMAX];
__device__ __align__(16) __nv_bfloat16 g_Wtlo[3 * HID * KMAX];
__device__ __align__(16) float g_pre[NN * HID];
__device__ __align__(16) float g_aggea[NN * ECH];
__device__ float g_deg[NN];
__device__ int   g_indeg[NN];
__device__ int   g_off[NN + 1];
__device__ int   g_pos[NN];
__device__ int   g_csrc[EE];
__device__ int   g_ceid[EE];
__device__ float g_statsA[2 * HID];
__device__ float g_statsB[2 * HID];
__device__ int   g_bcnt[BB];
__device__ int   g_boff[BB];
__device__ int   g_bar_arrive;
__device__ volatile int g_bar_gen;

// ---------------- helpers ----------------------------------------------------
__device__ __forceinline__ uint32_t smem_u32(const void* p) {
    uint32_t a;
    asm("{ .reg .u64 t; cvta.to.shared.u64 t, %1; cvt.u32.u64 %0, t; }" : "=r"(a) : "l"(p));
    return a;
}
__device__ __forceinline__ void ldm_x4(uint32_t* r, uint32_t addr) {
    asm volatile("ldmatrix.sync.aligned.m8n8.x4.shared.b16 {%0,%1,%2,%3}, [%4];"
                 : "=r"(r[0]), "=r"(r[1]), "=r"(r[2]), "=r"(r[3]) : "r"(addr));
}
__device__ __forceinline__ void mma_bf16(float* d, const uint32_t* a, const uint32_t* b) {
    asm volatile("mma.sync.aligned.m16n8k16.row.col.f32.bf16.bf16.f32 "
                 "{%0,%1,%2,%3}, {%4,%5,%6,%7}, {%8,%9}, {%0,%1,%2,%3};"
                 : "+f"(d[0]), "+f"(d[1]), "+f"(d[2]), "+f"(d[3])
                 : "r"(a[0]), "r"(a[1]), "r"(a[2]), "r"(a[3]), "r"(b[0]), "r"(b[1]));
}
__device__ __forceinline__ void cpa16(uint32_t dst, const void* src, int nbytes) {
    asm volatile("cp.async.cg.shared.global [%0], [%1], 16, %2;"
                 :: "r"(dst), "l"(src), "r"(nbytes) : "memory");
}
__device__ __forceinline__ void cpa_commit() { asm volatile("cp.async.commit_group;" ::: "memory"); }
__device__ __forceinline__ void cpa_wait0()  { asm volatile("cp.async.wait_group 0;" ::: "memory"); }
__device__ __forceinline__ unsigned short bfu(__nv_bfloat16 h) {
    return *reinterpret_cast<unsigned short*>(&h);
}
__device__ __forceinline__ void split1(float x, unsigned short& h, unsigned short& l) {
    __nv_bfloat16 hi = __float2bfloat16_rn(x);
    __nv_bfloat16 lo = __float2bfloat16_rn(x - __bfloat162float(hi));
    h = bfu(hi); l = bfu(lo);
}
__device__ __forceinline__ void split4_store(float4 v, size_t off) {
    unsigned short h0, l0, h1, l1, h2, l2, h3, l3;
    split1(v.x, h0, l0); split1(v.y, h1, l1); split1(v.z, h2, l2); split1(v.w, h3, l3);
    uint2 uh, ul;
    uh.x = (uint32_t)h0 | ((uint32_t)h1 << 16);
    uh.y = (uint32_t)h2 | ((uint32_t)h3 << 16);
    ul.x = (uint32_t)l0 | ((uint32_t)l1 << 16);
    ul.y = (uint32_t)l2 | ((uint32_t)l3 << 16);
    *(uint2*)(g_Xhi + off) = uh;
    *(uint2*)(g_Xlo + off) = ul;
}
__device__ __forceinline__ void add4(float4& a, float4 b) {
    a.x += b.x; a.y += b.y; a.z += b.z; a.w += b.w;
}
__device__ __forceinline__ float4 bnrelu4(float4 u, float4 sc, float4 sh) {
    float4 o;
    o.x = fmaxf(fmaf(u.x, sc.x, sh.x), 0.f);
    o.y = fmaxf(fmaf(u.y, sc.y, sh.y), 0.f);
    o.z = fmaxf(fmaf(u.z, sc.z, sh.z), 0.f);
    o.w = fmaxf(fmaf(u.w, sc.w, sh.w), 0.f);
    return o;
}

// generational grid barrier (grid sized to co-resident capacity by host)
__device__ __forceinline__ void gbar() {
    __syncthreads();
    if (threadIdx.x == 0) {
        __threadfence();                      // release (+ L1D invalidate on sm_103)
        int gen = g_bar_gen;
        if (atomicAdd(&g_bar_arrive, 1) == (int)gridDim.x - 1) {
            g_bar_arrive = 0;
            __threadfence();
            g_bar_gen = gen + 1;
        } else {
            while (g_bar_gen == gen) __nanosleep(64);
        }
        __threadfence();                      // acquire (+ L1D invalidate)
    }
    __syncthreads();
}

// ---------------- GEMM phase (persistent over tiles) -------------------------
__device__ __forceinline__ void gemm_phase(uint32_t sb, int layer, int K,
                                           const float* __restrict__ bias,
                                           float* __restrict__ stats) {
    const __nv_bfloat16* wtHi = g_Wthi + (size_t)layer * HID * KMAX;
    const __nv_bfloat16* wtLo = g_Wtlo + (size_t)layer * HID * KMAX;
    const int tid = threadIdx.x;
    const int warp = tid >> 5, lane = tid & 31;
    const int wn0 = warp * 32;
    const int nchunks = K >> 5;

    for (int tile = blockIdx.x; tile < NTILES; tile += gridDim.x) {
        const int row0 = (tile >> 1) * BM;
        const int n0 = (tile & 1) * BN;
        __syncthreads();

        float acc[4][4][4];
#pragma unroll
        for (int mi = 0; mi < 4; mi++)
#pragma unroll
            for (int ni = 0; ni < 4; ni++)
#pragma unroll
                for (int r = 0; r < 4; r++) acc[mi][ni][r] = 0.f;

        const int ar = tid >> 1;
        const int ahB = (tid & 1) * 32;
        const int am = row0 + ar;
        const int a_bytes = (am < NN) ? 16 : 0;
        const int am_c = (am < NN) ? am : (NN - 1);
        const int bn = n0 + tid;

        const char* aHiBase = (const char*)g_Xhi + ((size_t)am_c * K) * 2 + ahB;
        const char* aLoBase = (const char*)g_Xlo + ((size_t)am_c * K) * 2 + ahB;
        const char* bHiBase = (const char*)wtHi + ((size_t)bn * K) * 2;
        const char* bLoBase = (const char*)wtLo + ((size_t)bn * K) * 2;
        const uint32_t aDst = ar * ASTR + ahB;
        const uint32_t bDst = tid * ASTR;

        {   // prefetch chunk 0 into buffer 0
            cpa16(sb + O_AHI + aDst,      aHiBase,      a_bytes);
            cpa16(sb + O_AHI + aDst + 16, aHiBase + 16, a_bytes);
            cpa16(sb + O_ALO + aDst,      aLoBase,      a_bytes);
            cpa16(sb + O_ALO + aDst + 16, aLoBase + 16, a_bytes);
#pragma unroll
            for (int jj = 0; jj < 4; jj++) {
                cpa16(sb + O_BHI + bDst + jj * 16, bHiBase + jj * 16, 16);
                cpa16(sb + O_BLO + bDst + jj * 16, bLoBase + jj * 16, 16);
            }
            cpa_commit();
        }

        for (int c = 0; c < nchunks; c++) {
            cpa_wait0();
            __syncthreads();
            if (c + 1 < nchunks) {
                uint32_t nb = sb + ((c + 1) & 1) * BUFSZ;
                const char* ph = aHiBase + (c + 1) * 64;
                const char* pl = aLoBase + (c + 1) * 64;
                cpa16(nb + O_AHI + aDst,      ph,      a_bytes);
                cpa16(nb + O_AHI + aDst + 16, ph + 16, a_bytes);
                cpa16(nb + O_ALO + aDst,      pl,      a_bytes);
                cpa16(nb + O_ALO + aDst + 16, pl + 16, a_bytes);
                const char* qh = bHiBase + (c + 1) * 64;
                const char* ql = bLoBase + (c + 1) * 64;
#pragma unroll
                for (int jj = 0; jj < 4; jj++) {
                    cpa16(nb + O_BHI + bDst + jj * 16, qh + jj * 16, 16);
                    cpa16(nb + O_BLO + bDst + jj * 16, ql + jj * 16, 16);
                }
                cpa_commit();
            }
            const uint32_t cb = sb + (c & 1) * BUFSZ;
            const uint32_t uAhi = cb + O_AHI, uAlo = cb + O_ALO;
            const uint32_t uBhi = cb + O_BHI, uBlo = cb + O_BLO;
#pragma unroll
            for (int kt = 0; kt < 2; kt++) {
                const uint32_t aoff = (uint32_t)((kt * 32) + ((lane >> 4) * 16));
                uint32_t ah[4][4], al[4][4];
#pragma unroll
                for (int mi = 0; mi < 4; mi++) {
                    uint32_t ra = (uint32_t)((mi * 16 + (lane & 15)) * ASTR) + aoff;
                    ldm_x4(ah[mi], uAhi + ra);
                    ldm_x4(al[mi], uAlo + ra);
                }
                uint32_t bh[8], bl[8];
#pragma unroll
                for (int bj = 0; bj < 2; bj++) {
                    int nrow = wn0 + (bj * 2 + (lane >> 4)) * 8 + (lane & 7);
                    uint32_t rb = (uint32_t)(nrow * ASTR) + (uint32_t)(kt * 32 + ((lane >> 3) & 1) * 16);
                    ldm_x4(&bh[bj * 4], uBhi + rb);
                    ldm_x4(&bl[bj * 4], uBlo + rb);
                }
#pragma unroll
                for (int mi = 0; mi < 4; mi++)
#pragma unroll
                    for (int ni = 0; ni < 4; ni++) {
                        mma_bf16(acc[mi][ni], ah[mi], &bh[ni * 2]);
                        mma_bf16(acc[mi][ni], al[mi], &bh[ni * 2]);
                        mma_bf16(acc[mi][ni], ah[mi], &bl[ni * 2]);
                    }
            }
        }

        // epilogue: relu(acc + deg*bias) + column stats
        const int rsub = lane >> 2;
        const int cpair = (lane & 3) * 2;
        float cs[4][2], cq[4][2];
#pragma unroll
        for (int ni = 0; ni < 4; ni++) { cs[ni][0] = cs[ni][1] = cq[ni][0] = cq[ni][1] = 0.f; }
#pragma unroll
        for (int mi = 0; mi < 4; mi++) {
            int m0 = row0 + mi * 16 + rsub;
            int m1 = m0 + 8;
            float dg0 = (m0 < NN) ? g_deg[m0] : 0.f;
            float dg1 = (m1 < NN) ? g_deg[m1] : 0.f;
#pragma unroll
            for (int ni = 0; ni < 4; ni++) {
                int col = n0 + wn0 + ni * 8 + cpair;
                float2 bb = *(const float2*)&bias[col];
                if (m0 < NN) {
                    float ox = fmaxf(acc[mi][ni][0] + dg0 * bb.x, 0.f);
                    float oy = fmaxf(acc[mi][ni][1] + dg0 * bb.y, 0.f);
                    float2 o = {ox, oy};
                    *(float2*)&g_pre[(size_t)m0 * HID + col] = o;
                    cs[ni][0] += ox; cq[ni][0] += ox * ox;
                    cs[ni][1] += oy; cq[ni][1] += oy * oy;
                }
                if (m1 < NN) {
                    float ox = fmaxf(acc[mi][ni][2] + dg1 * bb.x, 0.f);
                    float oy = fmaxf(acc[mi][ni][3] + dg1 * bb.y, 0.f);
                    float2 o = {ox, oy};
                    *(float2*)&g_pre[(size_t)m1 * HID + col] = o;
                    cs[ni][0] += ox; cq[ni][0] += ox * ox;
                    cs[ni][1] += oy; cq[ni][1] += oy * oy;
                }
            }
        }
#pragma unroll
        for (int ni = 0; ni < 4; ni++) {
            float s0 = cs[ni][0], s1v = cs[ni][1], q0 = cq[ni][0], q1 = cq[ni][1];
#pragma unroll
            for (int off = 16; off >= 4; off >>= 1) {
                s0  += __shfl_down_sync(0xFFFFFFFF, s0, off);
                s1v += __shfl_down_sync(0xFFFFFFFF, s1v, off);
                q0  += __shfl_down_sync(0xFFFFFFFF, q0, off);
                q1  += __shfl_down_sync(0xFFFFFFFF, q1, off);
            }
            if (lane < 4) {
                int col = n0 + wn0 + ni * 8 + lane * 2;
                atomicAdd(&stats[col], s0);
                atomicAdd(&stats[col + 1], s1v);
                atomicAdd(&stats[HID + col], q0);
                atomicAdd(&stats[HID + col + 1], q1);
            }
        }
    }
}

// ---------------- agg phase (layers 2/3, inline BN) --------------------------
__device__ __forceinline__ void aggbn_phase(const float* __restrict__ gamma,
                                            const float* __restrict__ beta,
                                            const float* __restrict__ stats) {
    const int tid = threadIdx.x;
    const int slot = tid >> 6;          // 0..1
    const int t2 = tid & 63;
    const int c = t2 * 4;
    float4 sc, sh;
    {
        const float inv_n = 1.0f / (float)NN;
#pragma unroll
        for (int jj = 0; jj < 4; jj++) {
            float s = stats[c + jj];
            float q = stats[HID + c + jj];
            float mu = s * inv_n;
            float var = q * inv_n - mu * mu;
            float r = rsqrtf(var + 1e-5f);
            float scj = r * gamma[c + jj];
            ((float*)&sc)[jj] = scj;
            ((float*)&sh)[jj] = beta[c + jj] - mu * scj;
        }
    }
    for (int node = blockIdx.x * 2 + slot; node < NN; node += gridDim.x * 2) {
        int s0 = g_off[node], s1 = g_off[node + 1];
        float4 hv = bnrelu4(*(const float4*)&g_pre[(size_t)node * HID + c], sc, sh);
        float4 acc = hv;
        int j = s0;
        for (; j + 4 <= s1; j += 4) {
            int i0 = g_csrc[j], i1 = g_csrc[j + 1], i2 = g_csrc[j + 2], i3 = g_csrc[j + 3];
            float4 u0 = *(const float4*)&g_pre[(size_t)i0 * HID + c];
            float4 u1 = *(const float4*)&g_pre[(size_t)i1 * HID + c];
            float4 u2 = *(const float4*)&g_pre[(size_t)i2 * HID + c];
            float4 u3 = *(const float4*)&g_pre[(size_t)i3 * HID + c];
            add4(acc, bnrelu4(u0, sc, sh));
            add4(acc, bnrelu4(u1, sc, sh));
            add4(acc, bnrelu4(u2, sc, sh));
            add4(acc, bnrelu4(u3, sc, sh));
        }
        for (; j < s1; j++) {
            int s = g_csrc[j];
            add4(acc, bnrelu4(*(const float4*)&g_pre[(size_t)s * HID + c], sc, sh));
        }
        float dg = g_deg[node];
        float4 dv = make_float4(dg * hv.x, dg * hv.y, dg * hv.z, dg * hv.w);
        size_t rb = (size_t)node * 576;
        split4_store(dv, rb + c);
        split4_store(acc, rb + HID + c);
        if (t2 < ECH / 4) {
            float4 e4 = *(const float4*)&g_aggea[node * ECH + c];
            split4_store(e4, rb + 2 * HID + c);
        }
    }
}

// ---------------- the mega-kernel --------------------------------------------
extern "C" __global__ void __launch_bounds__(128, 2)
k_mega(const float* __restrict__ x, const int* __restrict__ ei,
       const float* __restrict__ ea, const int* __restrict__ batch,
       const float* __restrict__ neighbor,
       const float* __restrict__ W1, const float* __restrict__ b1,
       const float* __restrict__ g1, const float* __restrict__ be1,
       const float* __restrict__ W2, const float* __restrict__ b2,
       const float* __restrict__ g2, const float* __restrict__ be2,
       const float* __restrict__ W3, const float* __restrict__ b3,
       const float* __restrict__ g3, const float* __restrict__ be3,
       const float* __restrict__ fc1w, const float* __restrict__ fc1b,
       const float* __restrict__ fc2w, const float* __restrict__ fc2b,
       float* __restrict__ out) {
    extern __shared__ __align__(16) uint8_t dyn[];
    const uint32_t sb = smem_u32(dyn);
    const int tid = threadIdx.x;
    const int NB = gridDim.x;
    const int NT = NB * 128;
    const int gtid = blockIdx.x * 128 + tid;
    const int* src = ei;
    const int* dst = ei + EE;

    // ---- P0: zero + weight prep ----
    for (int i = gtid; i < NN; i += NT) g_indeg[i] = 0;
    for (int i = gtid; i < BB; i += NT) g_bcnt[i] = 0;
    for (int i = gtid; i < 2 * HID; i += NT) { g_statsA[i] = 0.f; g_statsB[i] = 0.f; }
#pragma unroll
    for (int li = 0; li < 3; li++) {
        const float* W = (li == 0) ? W1 : (li == 1 ? W2 : W3);
        int K = (li == 0) ? 320 : 576;
        for (int i = gtid; i < K * HID; i += NT) {
            int k = i >> 8, n = i & (HID - 1);
            unsigned short h, l;
            split1(W[i], h, l);
            size_t o = (size_t)li * HID * KMAX + (size_t)n * K + k;
            *reinterpret_cast<unsigned short*>(&g_Wthi[o]) = h;
            *reinterpret_cast<unsigned short*>(&g_Wtlo[o]) = l;
        }
    }
    gbar();

    // ---- P1: histograms ----
    for (int e = gtid; e < EE; e += NT) atomicAdd(&g_indeg[dst[e]], 1);
    for (int i = gtid; i < NN; i += NT) atomicAdd(&g_bcnt[batch[i]], 1);
    gbar();

    // ---- P2: scan (CTA 0) ----
    if (blockIdx.x == 0) {
        __shared__ int s_ws[4];
        int lane = tid & 31, w = tid >> 5;
        int carry = 0;
        for (int base = 0; base < NN; base += 128) {
            int idx = base + tid;
            int v = (idx < NN) ? g_indeg[idx] : 0;
            int inc = v;
#pragma unroll
            for (int o = 1; o < 32; o <<= 1) {
                int n = __shfl_up_sync(0xFFFFFFFF, inc, o);
                if (lane >= o) inc += n;
            }
            if (lane == 31) s_ws[w] = inc;
            __syncthreads();
            int add = 0;
#pragma unroll
            for (int ww = 0; ww < 3; ww++) if (ww < w) add += s_ws[ww];
            int tot = s_ws[0] + s_ws[1] + s_ws[2] + s_ws[3];
            int excl = carry + add + inc - v;
            if (idx < NN) {
                g_off[idx] = excl;
                g_pos[idx] = excl;
                g_deg[idx] = (float)(v + 1);
            }
            carry += tot;
            __syncthreads();
        }
        if (tid == 0) {
            g_off[NN] = carry;
            int cacc = 0;
            for (int b = 0; b < BB; b++) { g_boff[b] = cacc; cacc += g_bcnt[b]; }
        }
    }
    gbar();

    // ---- P3: CSR fill ----
    for (int e = gtid; e < EE; e += NT) {
        int d = dst[e];
        int p = atomicAdd(&g_pos[d], 1);
        g_csrc[p] = src[e];
        g_ceid[p] = e;
    }
    gbar();

    // ---- P4: layer-1 aggregation (x + edge_attr) ----
    {
        const int slot = tid >> 5;     // 0..3
        const int t4 = tid & 31;
        const int c = t4 * 4;
        const bool do_ea = t4 < (ECH / 4);
        for (int node = blockIdx.x * 4 + slot; node < NN; node += NB * 4) {
            int s0 = g_off[node], s1 = g_off[node + 1];
            float4 hv = *(const float4*)&x[(size_t)node * IN_C + c];
            float4 acc = hv;
            float4 eacc = make_float4(1.f, 1.f, 1.f, 1.f);
            int j = s0;
            for (; j + 4 <= s1; j += 4) {
                int i0 = g_csrc[j], i1 = g_csrc[j + 1], i2 = g_csrc[j + 2], i3 = g_csrc[j + 3];
                float4 u0 = *(const float4*)&x[(size_t)i0 * IN_C + c];
                float4 u1 = *(const float4*)&x[(size_t)i1 * IN_C + c];
                float4 u2 = *(const float4*)&x[(size_t)i2 * IN_C + c];
                float4 u3 = *(const float4*)&x[(size_t)i3 * IN_C + c];
                if (do_ea) {
                    int e0 = g_ceid[j], e1 = g_ceid[j + 1], e2 = g_ceid[j + 2], e3 = g_ceid[j + 3];
                    add4(eacc, *(const float4*)&ea[(size_t)e0 * ECH + c]);
                    add4(eacc, *(const float4*)&ea[(size_t)e1 * ECH + c]);
                    add4(eacc, *(const float4*)&ea[(size_t)e2 * ECH + c]);
                    add4(eacc, *(const float4*)&ea[(size_t)e3 * ECH + c]);
                }
                add4(acc, u0); add4(acc, u1); add4(acc, u2); add4(acc, u3);
            }
            for (; j < s1; j++) {
                int s = g_csrc[j];
                add4(acc, *(const float4*)&x[(size_t)s * IN_C + c]);
                if (do_ea) add4(eacc, *(const float4*)&ea[(size_t)g_ceid[j] * ECH + c]);
            }
            float dg = g_deg[node];
            float4 dv = make_float4(dg * hv.x, dg * hv.y, dg * hv.z, dg * hv.w);
            size_t rb = (size_t)node * 320;
            split4_store(dv, rb + c);
            split4_store(acc, rb + IN_C + c);
            if (do_ea) {
                *(float4*)&g_aggea[node * ECH + c] = eacc;
                split4_store(eacc, rb + 2 * IN_C + c);
            }
        }
    }
    gbar();

    // ---- P5: GEMM layer 1 ----
    gemm_phase(sb, 0, 320, b1, g_statsA);
    gbar();

    // ---- P6: agg layer 2 (BN of layer1) ----
    aggbn_phase(g1, be1, g_statsA);
    gbar();

    // ---- P7: GEMM layer 2 ----
    gemm_phase(sb, 1, 576, b2, g_statsB);
    gbar();

    // ---- P8: agg layer 3 (BN of layer2) + re-zero statsA for layer3 ----
    for (int i = gtid; i < 2 * HID; i += NT) g_statsA[i] = 0.f;
    aggbn_phase(g2, be2, g_statsB);
    gbar();

    // ---- P9: GEMM layer 3 ----
    gemm_phase(sb, 2, 576, b3, g_statsA);
    gbar();

    // ---- P10: pool(+BN3) -> fc1 -> fc2 ----
    {
        float* zs = (float*)dyn;             // 385 floats
        float* s1 = zs + 512;                // 512 floats
        const float inv_n = 1.0f / (float)NN;
        for (int b = blockIdx.x; b < BB; b += NB) {
            int boff = g_boff[b], cnt = g_bcnt[b];
            // pool: 2 channels per thread
#pragma unroll
            for (int half = 0; half < 2; half++) {
                int ch = tid + half * 128;
                float s = g_statsA[ch], q = g_statsA[HID + ch];
                float mu = s * inv_n;
                float var = q * inv_n - mu * mu;
                float r = rsqrtf(var + 1e-5f);
                float sc = r * g3[ch];
                float sh = be3[ch] - mu * sc;
                float accp = 0.f;
                for (int rr = 0; rr < cnt; rr++) {
                    float v = g_pre[(size_t)(boff + rr) * HID + ch];
                    accp += fmaxf(fmaf(v, sc, sh), 0.f);
                }
                zs[ch] = accp;
            }
            if (tid == 0) zs[HID] = (float)cnt / 40.0f;
            zs[HID + 1 + tid] = neighbor[b * IN_C + tid];   // tid < 128 = IN_C
            __syncthreads();
            // fc1: 4 outputs per thread
#pragma unroll
            for (int oo = 0; oo < 4; oo++) {
                int o = tid + oo * 128;
                float acc = fc1b[o];
                for (int k = 0; k < ZDIM; k++) acc = fmaf(zs[k], fc1w[(size_t)k * MLPD + o], acc);
                s1[o] = fmaxf(acc, 0.f);
            }
            __syncthreads();
            // fc2: 4 outputs, one warp each
            {
                int wrp = tid >> 5, lane = tid & 31;
                float a2 = 0.f;
                for (int k = lane; k < MLPD; k += 32)
                    a2 = fmaf(s1[k], fc2w[(size_t)k * NCL + wrp], a2);
#pragma unroll
                for (int o = 16; o > 0; o >>= 1) a2 += __shfl_down_sync(0xFFFFFFFF, a2, o);
                if (lane == 0) out[b * NCL + wrp] = a2 + fc2b[wrp];
            }
            __syncthreads();
        }
    }
}

// ---------------- launch -----------------------------------------------------
extern "C" void kernel_launch(void* const* d_in, const int* in_sizes, int n_in,
                              void* d_out, int out_size) {
    const float* x        = (const float*)d_in[0];
    const int*   ei       = (const int*)d_in[1];
    const float* ea       = (const float*)d_in[2];
    const int*   batch    = (const int*)d_in[3];
    const float* neighbor = (const float*)d_in[4];
    const float* W1  = (const float*)d_in[5];
    const float* b1  = (const float*)d_in[6];
    const float* g1  = (const float*)d_in[7];
    const float* be1 = (const float*)d_in[8];
    const float* W2  = (const float*)d_in[9];
    const float* b2  = (const float*)d_in[10];
    const float* g2  = (const float*)d_in[11];
    const float* be2 = (const float*)d_in[12];
    const float* W3  = (const float*)d_in[13];
    const float* b3  = (const float*)d_in[14];
    const float* g3  = (const float*)d_in[15];
    const float* be3 = (const float*)d_in[16];
    const float* fc1w = (const float*)d_in[17];
    const float* fc1b = (const float*)d_in[18];
    const float* fc2w = (const float*)d_in[19];
    const float* fc2b = (const float*)d_in[20];
    float* out = (float*)d_out;

    cudaFuncSetAttribute(k_mega, cudaFuncAttributeMaxDynamicSharedMemorySize, GEMM_SMEM);

    int nb = 0;
    cudaOccupancyMaxActiveBlocksPerMultiprocessor(&nb, k_mega, 128, GEMM_SMEM);
    if (nb < 1) nb = 1;
    int sms = 0;
    cudaDeviceGetAttribute(&sms, cudaDevAttrMultiProcessorCount, 0);
    if (sms < 1) sms = 148;
    int grid = nb * sms;   // exactly co-resident capacity -> spin barrier is safe

    k_mega<<<grid, 128, GEMM_SMEM>>>(x, ei, ea, batch, neighbor,
                                     W1, b1, g1, be1, W2, b2, g2, be2,
                                     W3, b3, g3, be3,
                                     fc1w, fc1b, fc2w, fc2b, out);
}

// round 11
// speedup vs baseline: 1.2642x; 1.2642x over previous
#include <cuda_runtime.h>
#include <cuda_bf16.h>
#include <cstdint>

// Problem constants
#define NN   10000
#define EE   320000
#define BB   64
#define IN_C 128
#define ECH  64
#define HID  256
#define MLPD 512
#define NCL  4
#define KMAX 576
#define ZDIM (HID + 1 + IN_C)   // 385

// GEMM tiling
#define BM 64
#define BN 128
#define ASTR 80
#define O_AHI 0
#define O_ALO (BM * ASTR)
#define O_BHI (2 * BM * ASTR)
#define O_BLO (2 * BM * ASTR + BN * ASTR)
#define BUFSZ (2 * BM * ASTR + 2 * BN * ASTR)   // 30720
#define GEMM_SMEM (2 * BUFSZ)                   // 61440

// ---------------- scratch ----------------------------------------------------
__device__ __align__(16) __nv_bfloat16 g_Xhi[NN * KMAX];
__device__ __align__(16) __nv_bfloat16 g_Xlo[NN * KMAX];
__device__ __align__(16) __nv_bfloat16 g_Wthi[3 * HID * KMAX];
__device__ __align__(16) __nv_bfloat16 g_Wtlo[3 * HID * KMAX];
__device__ __align__(16) float g_pre[NN * HID];
__device__ __align__(16) float g_aggea[NN * ECH];
__device__ float g_deg[NN];
__device__ int   g_indeg[NN];
__device__ int   g_off[NN + 1];
__device__ int   g_pos[NN];
__device__ int   g_csrc[EE];
__device__ int   g_ceid[EE];
__device__ float g_statsA[2 * HID];
__device__ float g_statsB[2 * HID];
__device__ int   g_bcnt[BB];
__device__ int   g_boff[BB];

// ---------------- helpers ----------------------------------------------------
__device__ __forceinline__ uint32_t smem_u32(const void* p) {
    uint32_t a;
    asm("{ .reg .u64 t; cvta.to.shared.u64 t, %1; cvt.u32.u64 %0, t; }" : "=r"(a) : "l"(p));
    return a;
}
__device__ __forceinline__ void ldm_x4(uint32_t* r, uint32_t addr) {
    asm volatile("ldmatrix.sync.aligned.m8n8.x4.shared.b16 {%0,%1,%2,%3}, [%4];"
                 : "=r"(r[0]), "=r"(r[1]), "=r"(r[2]), "=r"(r[3]) : "r"(addr));
}
__device__ __forceinline__ void mma_bf16(float* d, const uint32_t* a, const uint32_t* b) {
    asm volatile("mma.sync.aligned.m16n8k16.row.col.f32.bf16.bf16.f32 "
                 "{%0,%1,%2,%3}, {%4,%5,%6,%7}, {%8,%9}, {%0,%1,%2,%3};"
                 : "+f"(d[0]), "+f"(d[1]), "+f"(d[2]), "+f"(d[3])
                 : "r"(a[0]), "r"(a[1]), "r"(a[2]), "r"(a[3]), "r"(b[0]), "r"(b[1]));
}
__device__ __forceinline__ void cpa16(uint32_t dst, const void* src, int nbytes) {
    asm volatile("cp.async.cg.shared.global [%0], [%1], 16, %2;"
                 :: "r"(dst), "l"(src), "r"(nbytes) : "memory");
}
__device__ __forceinline__ void cpa_commit() { asm volatile("cp.async.commit_group;" ::: "memory"); }
__device__ __forceinline__ void cpa_wait0()  { asm volatile("cp.async.wait_group 0;" ::: "memory"); }
__device__ __forceinline__ unsigned short bfu(__nv_bfloat16 h) {
    return *reinterpret_cast<unsigned short*>(&h);
}
__device__ __forceinline__ void split1(float x, unsigned short& h, unsigned short& l) {
    __nv_bfloat16 hi = __float2bfloat16_rn(x);
    __nv_bfloat16 lo = __float2bfloat16_rn(x - __bfloat162float(hi));
    h = bfu(hi); l = bfu(lo);
}
__device__ __forceinline__ void split4_store(float4 v, size_t off) {
    unsigned short h0, l0, h1, l1, h2, l2, h3, l3;
    split1(v.x, h0, l0); split1(v.y, h1, l1); split1(v.z, h2, l2); split1(v.w, h3, l3);
    uint2 uh, ul;
    uh.x = (uint32_t)h0 | ((uint32_t)h1 << 16);
    uh.y = (uint32_t)h2 | ((uint32_t)h3 << 16);
    ul.x = (uint32_t)l0 | ((uint32_t)l1 << 16);
    ul.y = (uint32_t)l2 | ((uint32_t)l3 << 16);
    *(uint2*)(g_Xhi + off) = uh;
    *(uint2*)(g_Xlo + off) = ul;
}
__device__ __forceinline__ void add4(float4& a, float4 b) {
    a.x += b.x; a.y += b.y; a.z += b.z; a.w += b.w;
}
__device__ __forceinline__ float4 bnrelu4(float4 u, float4 sc, float4 sh) {
    float4 o;
    o.x = fmaxf(fmaf(u.x, sc.x, sh.x), 0.f);
    o.y = fmaxf(fmaf(u.y, sc.y, sh.y), 0.f);
    o.z = fmaxf(fmaf(u.z, sc.z, sh.z), 0.f);
    o.w = fmaxf(fmaf(u.w, sc.w, sh.w), 0.f);
    return o;
}

// ---------------- setup: zero + weight prep (fused) ---------------------------
__global__ void k_setup(const float* __restrict__ W1, const float* __restrict__ W2,
                        const float* __restrict__ W3) {
    int gt = blockIdx.x * 256 + threadIdx.x;
    int NT = gridDim.x * 256;
    for (int i = gt; i < NN; i += NT) g_indeg[i] = 0;
    if (gt < BB) g_bcnt[gt] = 0;
#pragma unroll
    for (int li = 0; li < 3; li++) {
        const float* W = (li == 0) ? W1 : (li == 1 ? W2 : W3);
        int K = (li == 0) ? 320 : 576;
        for (int i = gt; i < K * HID; i += NT) {
            int k = i >> 8, n = i & (HID - 1);
            unsigned short h, l;
            split1(W[i], h, l);
            size_t o = (size_t)li * HID * KMAX + (size_t)n * K + k;
            *reinterpret_cast<unsigned short*>(&g_Wthi[o]) = h;
            *reinterpret_cast<unsigned short*>(&g_Wtlo[o]) = l;
        }
    }
}

__global__ void k_hist(const int* __restrict__ dst, const int* __restrict__ batch) {
    int i = blockIdx.x * blockDim.x + threadIdx.x;
    if (i < EE) atomicAdd(&g_indeg[dst[i]], 1);
    if (i < NN) atomicAdd(&g_bcnt[batch[i]], 1);
}

__global__ void k_scan() {
    __shared__ int wsum[32];
    int t = threadIdx.x;               // 1024
    int lane = t & 31, wd = t >> 5;
    int vals[10];
    int s = 0;
    int base = t * 10;
#pragma unroll
    for (int i = 0; i < 10; i++) {
        int idx = base + i;
        int v = (idx < NN) ? g_indeg[idx] : 0;
        vals[i] = v;
        s += v;
    }
    int inc = s;
#pragma unroll
    for (int o = 1; o < 32; o <<= 1) {
        int n = __shfl_up_sync(0xFFFFFFFF, inc, o);
        if (lane >= o) inc += n;
    }
    if (lane == 31) wsum[wd] = inc;
    __syncthreads();
    if (wd == 0) {
        int x = wsum[lane];
#pragma unroll
        for (int o = 1; o < 32; o <<= 1) {
            int n = __shfl_up_sync(0xFFFFFFFF, x, o);
            if (lane >= o) x += n;
        }
        wsum[lane] = x;
    }
    __syncthreads();
    int off = inc - s + (wd ? wsum[wd - 1] : 0);
#pragma unroll
    for (int i = 0; i < 10; i++) {
        int idx = base + i;
        if (idx < NN) {
            g_off[idx] = off;
            g_pos[idx] = off;
            g_deg[idx] = (float)(vals[i] + 1);
        }
        off += vals[i];
    }
    if (t == 0) {
        g_off[NN] = EE;
        int c = 0;
        for (int b = 0; b < BB; b++) { g_boff[b] = c; c += g_bcnt[b]; }
    }
}

__global__ void k_fill(const int* __restrict__ src, const int* __restrict__ dst) {
    int e = blockIdx.x * blockDim.x + threadIdx.x;
    if (e >= EE) return;
    int d = dst[e];
    int p = atomicAdd(&g_pos[d], 1);
    g_csrc[p] = src[e];
    g_ceid[p] = e;
}

// ---------------- layer 1 agg: features + edge_attr fused --------------------
__global__ void __launch_bounds__(128) k_agg1(const float* __restrict__ x,
                                              float* __restrict__ zeroStats,
                                              const float* __restrict__ ea) {
    int tid = threadIdx.x;
    if (blockIdx.x == 0) {
        for (int i = tid; i < 2 * HID; i += 128) zeroStats[i] = 0.f;
    }
    int node = blockIdx.x * 4 + (tid >> 5);
    int t4 = tid & 31;
    int c = t4 * 4;
    int s0 = g_off[node], s1 = g_off[node + 1];

    float4 hv = *(const float4*)&x[(size_t)node * IN_C + c];
    float4 acc = hv;
    float4 eacc = make_float4(1.f, 1.f, 1.f, 1.f);
    const bool do_ea = t4 < (ECH / 4);

    int j = s0;
    for (; j + 8 <= s1; j += 8) {
        int i0 = g_csrc[j],     i1 = g_csrc[j + 1], i2 = g_csrc[j + 2], i3 = g_csrc[j + 3];
        int i4 = g_csrc[j + 4], i5 = g_csrc[j + 5], i6 = g_csrc[j + 6], i7 = g_csrc[j + 7];
        float4 u0 = *(const float4*)&x[(size_t)i0 * IN_C + c];
        float4 u1 = *(const float4*)&x[(size_t)i1 * IN_C + c];
        float4 u2 = *(const float4*)&x[(size_t)i2 * IN_C + c];
        float4 u3 = *(const float4*)&x[(size_t)i3 * IN_C + c];
        float4 u4 = *(const float4*)&x[(size_t)i4 * IN_C + c];
        float4 u5 = *(const float4*)&x[(size_t)i5 * IN_C + c];
        float4 u6 = *(const float4*)&x[(size_t)i6 * IN_C + c];
        float4 u7 = *(const float4*)&x[(size_t)i7 * IN_C + c];
        if (do_ea) {
            int e0 = g_ceid[j],     e1 = g_ceid[j + 1], e2 = g_ceid[j + 2], e3 = g_ceid[j + 3];
            int e4 = g_ceid[j + 4], e5 = g_ceid[j + 5], e6 = g_ceid[j + 6], e7 = g_ceid[j + 7];
            add4(eacc, *(const float4*)&ea[(size_t)e0 * ECH + c]);
            add4(eacc, *(const float4*)&ea[(size_t)e1 * ECH + c]);
            add4(eacc, *(const float4*)&ea[(size_t)e2 * ECH + c]);
            add4(eacc, *(const float4*)&ea[(size_t)e3 * ECH + c]);
            add4(eacc, *(const float4*)&ea[(size_t)e4 * ECH + c]);
            add4(eacc, *(const float4*)&ea[(size_t)e5 * ECH + c]);
            add4(eacc, *(const float4*)&ea[(size_t)e6 * ECH + c]);
            add4(eacc, *(const float4*)&ea[(size_t)e7 * ECH + c]);
        }
        add4(acc, u0); add4(acc, u1); add4(acc, u2); add4(acc, u3);
        add4(acc, u4); add4(acc, u5); add4(acc, u6); add4(acc, u7);
    }
    for (; j < s1; j++) {
        int s = g_csrc[j];
        add4(acc, *(const float4*)&x[(size_t)s * IN_C + c]);
        if (do_ea) add4(eacc, *(const float4*)&ea[(size_t)g_ceid[j] * ECH + c]);
    }

    float dg = g_deg[node];
    float4 dv = make_float4(dg * hv.x, dg * hv.y, dg * hv.z, dg * hv.w);
    size_t rb = (size_t)node * 320;
    split4_store(dv, rb + c);
    split4_store(acc, rb + IN_C + c);
    if (do_ea) {
        *(float4*)&g_aggea[node * ECH + c] = eacc;
        split4_store(eacc, rb + 2 * IN_C + c);
    }
}

// ---------------- layers 2/3 agg with inline BN of previous layer ------------
__global__ void __launch_bounds__(128) k_agg_bn(const float* __restrict__ gamma,
                                                const float* __restrict__ beta,
                                                const float* __restrict__ stats,
                                                float* __restrict__ zeroStats) {
    const float* feat = (const float*)g_pre;
    int tid = threadIdx.x;
    if (blockIdx.x == 0) {
        for (int i = tid; i < 2 * HID; i += 128) zeroStats[i] = 0.f;
    }
    int node = blockIdx.x * 2 + (tid >> 6);
    int t4 = tid & 63;
    int c = t4 * 4;

    float4 sc, sh;
    {
        const float inv_n = 1.0f / (float)NN;
#pragma unroll
        for (int jj = 0; jj < 4; jj++) {
            float s = stats[c + jj];
            float q = stats[HID + c + jj];
            float mu = s * inv_n;
            float var = q * inv_n - mu * mu;
            float r = rsqrtf(var + 1e-5f);
            float scj = r * gamma[c + jj];
            ((float*)&sc)[jj] = scj;
            ((float*)&sh)[jj] = beta[c + jj] - mu * scj;
        }
    }

    int s0 = g_off[node], s1 = g_off[node + 1];
    float4 hv = bnrelu4(*(const float4*)&feat[(size_t)node * HID + c], sc, sh);
    float4 acc = hv;

    int j = s0;
    for (; j + 8 <= s1; j += 8) {
        int i0 = g_csrc[j],     i1 = g_csrc[j + 1], i2 = g_csrc[j + 2], i3 = g_csrc[j + 3];
        int i4 = g_csrc[j + 4], i5 = g_csrc[j + 5], i6 = g_csrc[j + 6], i7 = g_csrc[j + 7];
        float4 u0 = *(const float4*)&feat[(size_t)i0 * HID + c];
        float4 u1 = *(const float4*)&feat[(size_t)i1 * HID + c];
        float4 u2 = *(const float4*)&feat[(size_t)i2 * HID + c];
        float4 u3 = *(const float4*)&feat[(size_t)i3 * HID + c];
        float4 u4 = *(const float4*)&feat[(size_t)i4 * HID + c];
        float4 u5 = *(const float4*)&feat[(size_t)i5 * HID + c];
        float4 u6 = *(const float4*)&feat[(size_t)i6 * HID + c];
        float4 u7 = *(const float4*)&feat[(size_t)i7 * HID + c];
        add4(acc, bnrelu4(u0, sc, sh)); add4(acc, bnrelu4(u1, sc, sh));
        add4(acc, bnrelu4(u2, sc, sh)); add4(acc, bnrelu4(u3, sc, sh));
        add4(acc, bnrelu4(u4, sc, sh)); add4(acc, bnrelu4(u5, sc, sh));
        add4(acc, bnrelu4(u6, sc, sh)); add4(acc, bnrelu4(u7, sc, sh));
    }
    for (; j < s1; j++) {
        int s = g_csrc[j];
        add4(acc, bnrelu4(*(const float4*)&feat[(size_t)s * HID + c], sc, sh));
    }

    float dg = g_deg[node];
    float4 dv = make_float4(dg * hv.x, dg * hv.y, dg * hv.z, dg * hv.w);
    size_t rb = (size_t)node * 576;
    split4_store(dv, rb + c);
    split4_store(acc, rb + HID + c);
    if (t4 < ECH / 4) {
        float4 e4 = *(const float4*)&g_aggea[node * ECH + c];
        split4_store(e4, rb + 2 * HID + c);
    }
}

// ---------------- GEMM (warp MMA, split bf16, cp.async double buffer) --------
__global__ void __launch_bounds__(128) k_gemm_mma(const float* __restrict__ bias, int K,
                                                  int layer, float* __restrict__ stats) {
    extern __shared__ __align__(16) uint8_t dyn[];
    const uint32_t sb = smem_u32(dyn);

    const __nv_bfloat16* wtHi = g_Wthi + (size_t)layer * HID * KMAX;
    const __nv_bfloat16* wtLo = g_Wtlo + (size_t)layer * HID * KMAX;

    const int tid = threadIdx.x;
    const int warp = tid >> 5, lane = tid & 31;
    const int row0 = blockIdx.x * BM;
    const int n0 = blockIdx.y * BN;
    const int wn0 = warp * 32;

    float acc[4][4][4];
#pragma unroll
    for (int mi = 0; mi < 4; mi++)
#pragma unroll
        for (int ni = 0; ni < 4; ni++)
#pragma unroll
            for (int r = 0; r < 4; r++) acc[mi][ni][r] = 0.f;

    const int ar = tid >> 1;
    const int ahB = (tid & 1) * 32;
    const int am = row0 + ar;
    const int a_bytes = (am < NN) ? 16 : 0;
    const int am_c = (am < NN) ? am : (NN - 1);
    const int bn = n0 + tid;

    const char* aHiBase = (const char*)g_Xhi + ((size_t)am_c * K) * 2 + ahB;
    const char* aLoBase = (const char*)g_Xlo + ((size_t)am_c * K) * 2 + ahB;
    const char* bHiBase = (const char*)wtHi + ((size_t)bn * K) * 2;
    const char* bLoBase = (const char*)wtLo + ((size_t)bn * K) * 2;
    const uint32_t aDst = ar * ASTR + ahB;
    const uint32_t bDst = tid * ASTR;

    const int nchunks = K >> 5;

    {   // prefetch chunk 0 into buffer 0
        cpa16(sb + O_AHI + aDst,      aHiBase,      a_bytes);
        cpa16(sb + O_AHI + aDst + 16, aHiBase + 16, a_bytes);
        cpa16(sb + O_ALO + aDst,      aLoBase,      a_bytes);
        cpa16(sb + O_ALO + aDst + 16, aLoBase + 16, a_bytes);
#pragma unroll
        for (int jj = 0; jj < 4; jj++) {
            cpa16(sb + O_BHI + bDst + jj * 16, bHiBase + jj * 16, 16);
            cpa16(sb + O_BLO + bDst + jj * 16, bLoBase + jj * 16, 16);
        }
        cpa_commit();
    }

    for (int c = 0; c < nchunks; c++) {
        cpa_wait0();
        __syncthreads();

        if (c + 1 < nchunks) {
            uint32_t nb = sb + ((c + 1) & 1) * BUFSZ;
            const char* ph = aHiBase + (c + 1) * 64;
            const char* pl = aLoBase + (c + 1) * 64;
            cpa16(nb + O_AHI + aDst,      ph,      a_bytes);
            cpa16(nb + O_AHI + aDst + 16, ph + 16, a_bytes);
            cpa16(nb + O_ALO + aDst,      pl,      a_bytes);
            cpa16(nb + O_ALO + aDst + 16, pl + 16, a_bytes);
            const char* qh = bHiBase + (c + 1) * 64;
            const char* ql = bLoBase + (c + 1) * 64;
#pragma unroll
            for (int jj = 0; jj < 4; jj++) {
                cpa16(nb + O_BHI + bDst + jj * 16, qh + jj * 16, 16);
                cpa16(nb + O_BLO + bDst + jj * 16, ql + jj * 16, 16);
            }
            cpa_commit();
        }

        const uint32_t cb = sb + (c & 1) * BUFSZ;
        const uint32_t uAhi = cb + O_AHI, uAlo = cb + O_ALO;
        const uint32_t uBhi = cb + O_BHI, uBlo = cb + O_BLO;

#pragma unroll
        for (int kt = 0; kt < 2; kt++) {
            const uint32_t aoff = (uint32_t)((kt * 32) + ((lane >> 4) * 16));
            uint32_t ah[4][4], al[4][4];
#pragma unroll
            for (int mi = 0; mi < 4; mi++) {
                uint32_t ra = (uint32_t)((mi * 16 + (lane & 15)) * ASTR) + aoff;
                ldm_x4(ah[mi], uAhi + ra);
                ldm_x4(al[mi], uAlo + ra);
            }
            uint32_t bh[8], bl[8];
#pragma unroll
            for (int bj = 0; bj < 2; bj++) {
                int nrow = wn0 + (bj * 2 + (lane >> 4)) * 8 + (lane & 7);
                uint32_t rb = (uint32_t)(nrow * ASTR) + (uint32_t)(kt * 32 + ((lane >> 3) & 1) * 16);
                ldm_x4(&bh[bj * 4], uBhi + rb);
                ldm_x4(&bl[bj * 4], uBlo + rb);
            }
#pragma unroll
            for (int mi = 0; mi < 4; mi++)
#pragma unroll
                for (int ni = 0; ni < 4; ni++) {
                    mma_bf16(acc[mi][ni], ah[mi], &bh[ni * 2]);
                    mma_bf16(acc[mi][ni], al[mi], &bh[ni * 2]);
                    mma_bf16(acc[mi][ni], ah[mi], &bl[ni * 2]);
                }
        }
    }

    // ---- epilogue: relu(acc + deg*bias) + column stats ----
    const int rsub = lane >> 2;
    const int cpair = (lane & 3) * 2;
    float cs[4][2], cq[4][2];
#pragma unroll
    for (int ni = 0; ni < 4; ni++) { cs[ni][0] = cs[ni][1] = cq[ni][0] = cq[ni][1] = 0.f; }

#pragma unroll
    for (int mi = 0; mi < 4; mi++) {
        int m0 = row0 + mi * 16 + rsub;
        int m1 = m0 + 8;
        float dg0 = (m0 < NN) ? g_deg[m0] : 0.f;
        float dg1 = (m1 < NN) ? g_deg[m1] : 0.f;
#pragma unroll
        for (int ni = 0; ni < 4; ni++) {
            int col = n0 + wn0 + ni * 8 + cpair;
            float2 bb = *(const float2*)&bias[col];
            if (m0 < NN) {
                float ox = fmaxf(acc[mi][ni][0] + dg0 * bb.x, 0.f);
                float oy = fmaxf(acc[mi][ni][1] + dg0 * bb.y, 0.f);
                float2 o = {ox, oy};
                *(float2*)&g_pre[(size_t)m0 * HID + col] = o;
                cs[ni][0] += ox; cq[ni][0] += ox * ox;
                cs[ni][1] += oy; cq[ni][1] += oy * oy;
            }
            if (m1 < NN) {
                float ox = fmaxf(acc[mi][ni][2] + dg1 * bb.x, 0.f);
                float oy = fmaxf(acc[mi][ni][3] + dg1 * bb.y, 0.f);
                float2 o = {ox, oy};
                *(float2*)&g_pre[(size_t)m1 * HID + col] = o;
                cs[ni][0] += ox; cq[ni][0] += ox * ox;
                cs[ni][1] += oy; cq[ni][1] += oy * oy;
            }
        }
    }
#pragma unroll
    for (int ni = 0; ni < 4; ni++) {
        float s0 = cs[ni][0], s1v = cs[ni][1], q0 = cq[ni][0], q1 = cq[ni][1];
#pragma unroll
        for (int off = 16; off >= 4; off >>= 1) {
            s0  += __shfl_down_sync(0xFFFFFFFF, s0, off);
            s1v += __shfl_down_sync(0xFFFFFFFF, s1v, off);
            q0  += __shfl_down_sync(0xFFFFFFFF, q0, off);
            q1  += __shfl_down_sync(0xFFFFFFFF, q1, off);
        }
        if (lane < 4) {
            int col = n0 + wn0 + ni * 8 + lane * 2;
            atomicAdd(&stats[col], s0);
            atomicAdd(&stats[col + 1], s1v);
            atomicAdd(&stats[HID + col], q0);
            atomicAdd(&stats[HID + col + 1], q1);
        }
    }
}

// ---------------- fused readout: pool(+BN) -> fc1 -> fc2 ---------------------
__global__ void __launch_bounds__(512) k_poolfc(const float* __restrict__ stats,
                                                const float* __restrict__ gamma,
                                                const float* __restrict__ beta,
                                                const float* __restrict__ neighbor,
                                                const float* __restrict__ fc1w,
                                                const float* __restrict__ fc1b,
                                                const float* __restrict__ fc2w,
                                                const float* __restrict__ fc2b,
                                                float* __restrict__ out) {
    __shared__ float zs[ZDIM];
    __shared__ float s1[MLPD];
    int b = blockIdx.x, t = threadIdx.x;
    int boff = g_boff[b], cnt = g_bcnt[b];

    if (t < HID) {
        const float inv_n = 1.0f / (float)NN;
        float s = stats[t], q = stats[HID + t];
        float mu = s * inv_n;
        float var = q * inv_n - mu * mu;
        float r = rsqrtf(var + 1e-5f);
        float sc = r * gamma[t];
        float sh = beta[t] - mu * sc;
        float accp = 0.f;
        const float* base = g_pre + (size_t)boff * HID + t;
        int rr = 0;
        for (; rr + 4 <= cnt; rr += 4) {
            float v0 = base[(size_t)(rr + 0) * HID];
            float v1 = base[(size_t)(rr + 1) * HID];
            float v2 = base[(size_t)(rr + 2) * HID];
            float v3 = base[(size_t)(rr + 3) * HID];
            accp += fmaxf(fmaf(v0, sc, sh), 0.f) + fmaxf(fmaf(v1, sc, sh), 0.f)
                  + fmaxf(fmaf(v2, sc, sh), 0.f) + fmaxf(fmaf(v3, sc, sh), 0.f);
        }
        for (; rr < cnt; rr++) accp += fmaxf(fmaf(base[(size_t)rr * HID], sc, sh), 0.f);
        zs[t] = accp;
    } else if (t == HID) {
        zs[HID] = (float)cnt / 40.0f;
    } else if (t < HID + 1 + IN_C + 1 && t >= HID + 1) {
        int j = t - (HID + 1);
        if (j < IN_C) zs[HID + 1 + j] = neighbor[b * IN_C + j];
    }
    __syncthreads();

    float acc = fc1b[t];
#pragma unroll 8
    for (int k = 0; k < ZDIM; k++) acc = fmaf(zs[k], fc1w[(size_t)k * MLPD + t], acc);
    s1[t] = fmaxf(acc, 0.f);
    __syncthreads();

    if (t < 128) {
        int wrp = t >> 5, lane = t & 31;
        float a2 = 0.f;
#pragma unroll 4
        for (int k = lane; k < MLPD; k += 32)
            a2 = fmaf(s1[k], fc2w[(size_t)k * NCL + wrp], a2);
#pragma unroll
        for (int o = 16; o > 0; o >>= 1) a2 += __shfl_down_sync(0xFFFFFFFF, a2, o);
        if (lane == 0) out[b * NCL + wrp] = a2 + fc2b[wrp];
    }
}

// ---------------- launch -----------------------------------------------------
extern "C" void kernel_launch(void* const* d_in, const int* in_sizes, int n_in,
                              void* d_out, int out_size) {
    const float* x        = (const float*)d_in[0];
    const int*   ei       = (const int*)d_in[1];
    const float* ea       = (const float*)d_in[2];
    const int*   batch    = (const int*)d_in[3];
    const float* neighbor = (const float*)d_in[4];
    const float* W1  = (const float*)d_in[5];
    const float* b1  = (const float*)d_in[6];
    const float* g1  = (const float*)d_in[7];
    const float* be1 = (const float*)d_in[8];
    const float* W2  = (const float*)d_in[9];
    const float* b2  = (const float*)d_in[10];
    const float* g2  = (const float*)d_in[11];
    const float* be2 = (const float*)d_in[12];
    const float* W3  = (const float*)d_in[13];
    const float* b3  = (const float*)d_in[14];
    const float* g3  = (const float*)d_in[15];
    const float* be3 = (const float*)d_in[16];
    const float* fc1w = (const float*)d_in[17];
    const float* fc1b = (const float*)d_in[18];
    const float* fc2w = (const float*)d_in[19];
    const float* fc2b = (const float*)d_in[20];
    float* out = (float*)d_out;

    const int* src = ei;
    const int* dst = ei + EE;

    float* statsA; float* statsB;
    cudaGetSymbolAddress((void**)&statsA, g_statsA);
    cudaGetSymbolAddress((void**)&statsB, g_statsB);

    cudaFuncSetAttribute(k_gemm_mma, cudaFuncAttributeMaxDynamicSharedMemorySize, GEMM_SMEM);

    // setup
    k_setup<<<592, 256>>>(W1, W2, W3);
    k_hist<<<(EE + 255) / 256, 256>>>(dst, batch);
    k_scan<<<1, 1024>>>();
    k_fill<<<(EE + 255) / 256, 256>>>(src, dst);

    dim3 ggrid((NN + BM - 1) / BM, HID / BN);
    int K1 = 2 * IN_C + ECH;   // 320
    int K23 = 2 * HID + ECH;   // 576

    // layer 1 (features + edge_attr fused)
    k_agg1<<<NN / 4, 128>>>(x, statsA, ea);
    k_gemm_mma<<<ggrid, 128, GEMM_SMEM>>>(b1, K1, 0, statsA);

    // layer 2
    k_agg_bn<<<NN / 2, 128>>>(g1, be1, statsA, statsB);
    k_gemm_mma<<<ggrid, 128, GEMM_SMEM>>>(b2, K23, 1, statsB);

    // layer 3
    k_agg_bn<<<NN / 2, 128>>>(g2, be2, statsB, statsA);
    k_gemm_mma<<<ggrid, 128, GEMM_SMEM>>>(b3, K23, 2, statsA);

    // readout
    k_poolfc<<<BB, 512>>>(statsA, g3, be3, neighbor, fc1w, fc1b, fc2w, fc2b, out);
}